// round 15
// baseline (speedup 1.0000x reference)
#include <cuda_runtime.h>

#define HID   100
#define G4    400
#define SEQ   8192
#define NCLS  20
#define TB    16
#define NTL   500      // 5 K-slices x 100 units; 16-warp alloc -> 128-reg cap
#define KS    20       // floats per K-slice (5*20 = 100, exact)

// scratch for x_proj, stored TRANSPOSED: xp4[t*100 + j] = (i,f,g,o) of unit j
// i/f/o entries PRE-HALVED (0.5x); g entry full scale.
// Padded by one timestep (+HID) so the last prefetch lands in-bounds.
__device__ float4 g_xp4[(SEQ + 1) * HID];

__device__ __forceinline__ unsigned long long ffma2(unsigned long long a,
                                                    unsigned long long b,
                                                    unsigned long long c) {
    unsigned long long d;
    asm("fma.rn.f32x2 %0, %1, %2, %3;" : "=l"(d) : "l"(a), "l"(b), "l"(c));
    return d;
}
__device__ __forceinline__ void unpack2(unsigned long long v, float& lo, float& hi) {
    asm("mov.b64 {%0, %1}, %2;" : "=f"(lo), "=f"(hi) : "l"(v));
}
__device__ __forceinline__ unsigned long long pack2(float lo, float hi) {
    unsigned long long v;
    asm("mov.b64 %0, {%1, %2};" : "=l"(v) : "f"(lo), "f"(hi));
    return v;
}
__device__ __forceinline__ float tanh_a(float x) {
    float y;
    asm("tanh.approx.f32 %0, %1;" : "=f"(y) : "f"(x));
    return y;
}

// ---------------------------------------------------------------------------
// Kernel 1: embedding gather + x_proj GEMM, TRANSPOSED output (i,f,g,o)/unit
// i/f/o outputs pre-scaled by 0.5 (sigmoid consumed as fma(0.5,tanh(p),0.5)).
// ---------------------------------------------------------------------------
__global__ void __launch_bounds__(G4, 1)
proj_kernel(const int* __restrict__ seq, const float* __restrict__ emb,
            const float* __restrict__ W_ih, const float* __restrict__ b_ih,
            const float* __restrict__ b_hh) {
    __shared__ float es[TB * HID];
    __shared__ int   sid[TB];
    const int tid = threadIdx.x;          // gate row r = g*100 + j
    const int t0  = blockIdx.x * TB;
    const int g   = tid / HID;
    const int j   = tid - g * HID;

    if (tid < TB) sid[tid] = seq[t0 + tid];
    __syncthreads();
    for (int n = tid; n < TB * HID; n += G4) {
        int tt = n / HID, k = n % HID;
        es[n] = emb[(long long)sid[tt] * HID + k];
    }
    __syncthreads();

    float acc[TB];
#pragma unroll
    for (int tt = 0; tt < TB; tt++) acc[tt] = 0.f;

    const float4* wr4 = (const float4*)(W_ih + tid * HID);
#pragma unroll 5
    for (int m = 0; m < 25; m++) {
        float4 wv = __ldg(&wr4[m]);
#pragma unroll
        for (int tt = 0; tt < TB; tt++) {
            const float* e = es + tt * HID + 4 * m;
            acc[tt] += wv.x * e[0] + wv.y * e[1] + wv.z * e[2] + wv.w * e[3];
        }
    }
    float b = b_ih[tid] + b_hh[tid];
    const float sc = (g == 2) ? 1.0f : 0.5f;   // pre-halve i/f/o
    float* xp = (float*)g_xp4;
#pragma unroll
    for (int tt = 0; tt < TB; tt++)
        xp[(t0 + tt) * G4 + j * 4 + g] = sc * (acc[tt] + b);   // transposed
}

// ---------------------------------------------------------------------------
// Kernel 2: LSTM recurrence — R14 body verbatim; changes (same lever):
//  * t-loop unrolled x4;
//  * xq prefetch via strength-reduced pointer: LDG with immediate offset
//    (k*HID entries), pointer bumped once per 4 steps; no per-step index
//    ALU on the owner's pre-barrier path. Last prefetch hits the +HID pad.
// ---------------------------------------------------------------------------

// one full timestep; K = step index within the unrolled group (0..3)
#define LSTM_STEP(K)                                                          \
    {                                                                         \
        float4 xq_n;                                                          \
        if (owner)                                                            \
            xq_n = __ldg(xqp + ((K) + 1) * HID);                              \
        unsigned long long a0 = 0ull, a1 = 0ull, a2 = 0ull, a3 = 0ull;        \
        _Pragma("unroll")                                                     \
        for (int m = 0; m < 5; m++) {                                         \
            ulonglong2 hv = h2s[m];                                           \
            a0 = ffma2(w2[2 * m],      hv.x, a0);                             \
            a0 = ffma2(w2[2 * m + 1],  hv.y, a0);                             \
            a1 = ffma2(w2[10 + 2 * m], hv.x, a1);                             \
            a1 = ffma2(w2[11 + 2 * m], hv.y, a1);                             \
            a2 = ffma2(w2[20 + 2 * m], hv.x, a2);                             \
            a2 = ffma2(w2[21 + 2 * m], hv.y, a2);                             \
            a3 = ffma2(w2[30 + 2 * m], hv.x, a3);                             \
            a3 = ffma2(w2[31 + 2 * m], hv.y, a3);                             \
        }                                                                     \
        float l0, h0, l1, h1, l2, h2v, l3, h3;                                \
        unpack2(a0, l0, h0);                                                  \
        unpack2(a1, l1, h1);                                                  \
        unpack2(a2, l2, h2v);                                                 \
        unpack2(a3, l3, h3);                                                  \
        float pi = l0 + h0, pf = l1 + h1, pg = l2 + h2v, po = l3 + h3;        \
        if (!owner) *pmy = make_float4(pi, pf, pg, po);                       \
        __syncthreads();                                                      \
        if (owner) {                                                          \
            float4 v1 = *pp1;                                                 \
            float4 v2 = *pp2;                                                 \
            float4 v3 = *pp3;                                                 \
            float4 v4 = *pp4;                                                 \
            pf += ((v1.y + v2.y) + (v3.y + v4.y)) + xq.y;                     \
            float fg = fmaf(0.5f, tanh_a(pf), 0.5f);                          \
            pi += ((v1.x + v2.x) + (v3.x + v4.x)) + xq.x;                     \
            pg += ((v1.z + v2.z) + (v3.z + v4.z)) + xq.z;                     \
            po += ((v1.w + v2.w) + (v3.w + v4.w)) + xq.w;                     \
            float ig = fmaf(0.5f, tanh_a(pi), 0.5f);                          \
            float gg = tanh_a(pg);                                            \
            float og = fmaf(0.5f, tanh_a(po), 0.5f);                          \
            c = fg * c + ig * gg;                                             \
            h_sh[j] = og * tanh_a(c);                                         \
            xq = xq_n;                                                        \
        }                                                                     \
        __syncthreads();                                                      \
    }

__global__ void __launch_bounds__(NTL, 1)
lstm_kernel(const float* __restrict__ W_hh,
            const float* __restrict__ fc_w, const float* __restrict__ fc_b,
            float* __restrict__ out) {
    __shared__ __align__(16) float h_sh[HID];
    __shared__ __align__(16) float4 part4[NTL];
    const int tid = threadIdx.x;
    const int s   = tid / HID;            // K-slice 0..4
    const int j   = tid - s * HID;        // unit 0..99
    const bool owner = (s == 0);

    // preload weights: 4 gate rows x 5 float4 chunks; i/f/o rows scaled 0.5
    unsigned long long w2[40];
#pragma unroll
    for (int g = 0; g < 4; g++) {
        const float sc = (g == 2) ? 1.0f : 0.5f;
        const float* wrow = W_hh + (g * HID + j) * HID + KS * s;
#pragma unroll
        for (int m = 0; m < 5; m++) {
            float4 v = *(const float4*)(wrow + 4 * m);
            w2[g * 10 + 2 * m]     = pack2(sc * v.x, sc * v.y);
            w2[g * 10 + 2 * m + 1] = pack2(sc * v.z, sc * v.w);
        }
    }

    if (tid < HID) h_sh[tid] = 0.f;
    float c = 0.f;
    __syncthreads();

    // loop-invariant pointers (hoisted once)
    const ulonglong2* h2s = (const ulonglong2*)h_sh + 5 * s;   // matvec slice
    float4* pmy = &part4[tid];                                  // worker store
    const float4* pp1 = &part4[1 * HID + j];                    // owner reads
    const float4* pp2 = &part4[2 * HID + j];
    const float4* pp3 = &part4[3 * HID + j];
    const float4* pp4 = &part4[4 * HID + j];

    const float4* xqp = &g_xp4[j];        // strength-reduced x_proj stream
    float4 xq = owner ? __ldg(xqp) : make_float4(0.f, 0.f, 0.f, 0.f);

    for (int t = 0; t < SEQ; t += 4) {
        LSTM_STEP(0)
        LSTM_STEP(1)
        LSTM_STEP(2)
        LSTM_STEP(3)
        xqp += 4 * HID;
    }

    // final FC
    if (tid < NCLS) {
        float sfc = fc_b[tid];
        const float* fw = fc_w + tid * HID;
#pragma unroll 4
        for (int k = 0; k < HID; k++) sfc += fw[k] * h_sh[k];
        out[tid] = sfc;
    }
}

// ---------------------------------------------------------------------------
extern "C" void kernel_launch(void* const* d_in, const int* in_sizes, int n_in,
                              void* d_out, int out_size) {
    const int*   seq  = (const int*)d_in[0];
    const float* emb  = (const float*)d_in[1];
    const float* W_ih = (const float*)d_in[2];
    const float* W_hh = (const float*)d_in[3];
    const float* b_ih = (const float*)d_in[4];
    const float* b_hh = (const float*)d_in[5];
    const float* fc_w = (const float*)d_in[6];
    const float* fc_b = (const float*)d_in[7];
    float* out = (float*)d_out;

    proj_kernel<<<SEQ / TB, G4>>>(seq, emb, W_ih, b_ih, b_hh);
    lstm_kernel<<<1, NTL>>>(W_hh, fc_w, fc_b, out);
}

// round 16
// speedup vs baseline: 1.1143x; 1.1143x over previous
#include <cuda_runtime.h>

#define HID   100
#define G4    400
#define SEQ   8192
#define NCLS  20
#define TB    16
#define NTL   500      // 5 K-slices x 100 units; 16-warp alloc -> 128-reg cap
#define KS    20       // floats per K-slice (5*20 = 100, exact)

// scratch for x_proj, stored TRANSPOSED: xp4[t*100 + j] = (i,f,g,o) of unit j
// i/f/o entries PRE-HALVED (0.5x); g entry full scale.
// Padded by one timestep so the t=SEQ-1 prefetch lands in-bounds (never used).
__device__ float4 g_xp4[(SEQ + 1) * HID];

__device__ __forceinline__ unsigned long long ffma2(unsigned long long a,
                                                    unsigned long long b,
                                                    unsigned long long c) {
    unsigned long long d;
    asm("fma.rn.f32x2 %0, %1, %2, %3;" : "=l"(d) : "l"(a), "l"(b), "l"(c));
    return d;
}
__device__ __forceinline__ void unpack2(unsigned long long v, float& lo, float& hi) {
    asm("mov.b64 {%0, %1}, %2;" : "=f"(lo), "=f"(hi) : "l"(v));
}
__device__ __forceinline__ unsigned long long pack2(float lo, float hi) {
    unsigned long long v;
    asm("mov.b64 %0, {%1, %2};" : "=l"(v) : "f"(lo), "f"(hi));
    return v;
}
__device__ __forceinline__ float tanh_a(float x) {
    float y;
    asm("tanh.approx.f32 %0, %1;" : "=f"(y) : "f"(x));
    return y;
}

// ---------------------------------------------------------------------------
// Kernel 1: embedding gather + x_proj GEMM, TRANSPOSED output (i,f,g,o)/unit
// i/f/o outputs pre-scaled by 0.5 (sigmoid consumed as fma(0.5,tanh(p),0.5)).
// ---------------------------------------------------------------------------
__global__ void __launch_bounds__(G4, 1)
proj_kernel(const int* __restrict__ seq, const float* __restrict__ emb,
            const float* __restrict__ W_ih, const float* __restrict__ b_ih,
            const float* __restrict__ b_hh) {
    __shared__ float es[TB * HID];
    __shared__ int   sid[TB];
    const int tid = threadIdx.x;          // gate row r = g*100 + j
    const int t0  = blockIdx.x * TB;
    const int g   = tid / HID;
    const int j   = tid - g * HID;

    if (tid < TB) sid[tid] = seq[t0 + tid];
    __syncthreads();
    for (int n = tid; n < TB * HID; n += G4) {
        int tt = n / HID, k = n % HID;
        es[n] = emb[(long long)sid[tt] * HID + k];
    }
    __syncthreads();

    float acc[TB];
#pragma unroll
    for (int tt = 0; tt < TB; tt++) acc[tt] = 0.f;

    const float4* wr4 = (const float4*)(W_ih + tid * HID);
#pragma unroll 5
    for (int m = 0; m < 25; m++) {
        float4 wv = __ldg(&wr4[m]);
#pragma unroll
        for (int tt = 0; tt < TB; tt++) {
            const float* e = es + tt * HID + 4 * m;
            acc[tt] += wv.x * e[0] + wv.y * e[1] + wv.z * e[2] + wv.w * e[3];
        }
    }
    float b = b_ih[tid] + b_hh[tid];
    const float sc = (g == 2) ? 1.0f : 0.5f;   // pre-halve i/f/o
    float* xp = (float*)g_xp4;
#pragma unroll
    for (int tt = 0; tt < TB; tt++)
        xp[(t0 + tt) * G4 + j * 4 + g] = sc * (acc[tt] + b);   // transposed
}

// ---------------------------------------------------------------------------
// Kernel 2: LSTM recurrence — R14 verbatim (x2 unroll, hoisted pointers),
// single change: prefetch index drops the & (SEQ-1) mask (pad absorbs the
// final out-of-range prefetch). One fewer dependent ALU op on the owner's
// pre-barrier path per step; zero change to register liveness.
// ---------------------------------------------------------------------------

// one full timestep; body identical to R14 minus the mask
#define LSTM_STEP(T)                                                          \
    {                                                                         \
        float4 xq_n;                                                          \
        if (owner)                                                            \
            xq_n = __ldg(&g_xp4[((T) + 1) * HID + j]);                        \
        unsigned long long a0 = 0ull, a1 = 0ull, a2 = 0ull, a3 = 0ull;        \
        _Pragma("unroll")                                                     \
        for (int m = 0; m < 5; m++) {                                         \
            ulonglong2 hv = h2s[m];                                           \
            a0 = ffma2(w2[2 * m],      hv.x, a0);                             \
            a0 = ffma2(w2[2 * m + 1],  hv.y, a0);                             \
            a1 = ffma2(w2[10 + 2 * m], hv.x, a1);                             \
            a1 = ffma2(w2[11 + 2 * m], hv.y, a1);                             \
            a2 = ffma2(w2[20 + 2 * m], hv.x, a2);                             \
            a2 = ffma2(w2[21 + 2 * m], hv.y, a2);                             \
            a3 = ffma2(w2[30 + 2 * m], hv.x, a3);                             \
            a3 = ffma2(w2[31 + 2 * m], hv.y, a3);                             \
        }                                                                     \
        float l0, h0, l1, h1, l2, h2v, l3, h3;                                \
        unpack2(a0, l0, h0);                                                  \
        unpack2(a1, l1, h1);                                                  \
        unpack2(a2, l2, h2v);                                                 \
        unpack2(a3, l3, h3);                                                  \
        float pi = l0 + h0, pf = l1 + h1, pg = l2 + h2v, po = l3 + h3;        \
        if (!owner) *pmy = make_float4(pi, pf, pg, po);                       \
        __syncthreads();                                                      \
        if (owner) {                                                          \
            float4 v1 = *pp1;                                                 \
            float4 v2 = *pp2;                                                 \
            float4 v3 = *pp3;                                                 \
            float4 v4 = *pp4;                                                 \
            pf += ((v1.y + v2.y) + (v3.y + v4.y)) + xq.y;                     \
            float fg = fmaf(0.5f, tanh_a(pf), 0.5f);                          \
            pi += ((v1.x + v2.x) + (v3.x + v4.x)) + xq.x;                     \
            pg += ((v1.z + v2.z) + (v3.z + v4.z)) + xq.z;                     \
            po += ((v1.w + v2.w) + (v3.w + v4.w)) + xq.w;                     \
            float ig = fmaf(0.5f, tanh_a(pi), 0.5f);                          \
            float gg = tanh_a(pg);                                            \
            float og = fmaf(0.5f, tanh_a(po), 0.5f);                          \
            c = fg * c + ig * gg;                                             \
            h_sh[j] = og * tanh_a(c);                                         \
            xq = xq_n;                                                        \
        }                                                                     \
        __syncthreads();                                                      \
    }

__global__ void __launch_bounds__(NTL, 1)
lstm_kernel(const float* __restrict__ W_hh,
            const float* __restrict__ fc_w, const float* __restrict__ fc_b,
            float* __restrict__ out) {
    __shared__ __align__(16) float h_sh[HID];
    __shared__ __align__(16) float4 part4[NTL];
    const int tid = threadIdx.x;
    const int s   = tid / HID;            // K-slice 0..4
    const int j   = tid - s * HID;        // unit 0..99
    const bool owner = (s == 0);

    // preload weights: 4 gate rows x 5 float4 chunks; i/f/o rows scaled 0.5
    unsigned long long w2[40];
#pragma unroll
    for (int g = 0; g < 4; g++) {
        const float sc = (g == 2) ? 1.0f : 0.5f;
        const float* wrow = W_hh + (g * HID + j) * HID + KS * s;
#pragma unroll
        for (int m = 0; m < 5; m++) {
            float4 v = *(const float4*)(wrow + 4 * m);
            w2[g * 10 + 2 * m]     = pack2(sc * v.x, sc * v.y);
            w2[g * 10 + 2 * m + 1] = pack2(sc * v.z, sc * v.w);
        }
    }

    if (tid < HID) h_sh[tid] = 0.f;
    float c = 0.f;
    __syncthreads();

    // loop-invariant pointers (hoisted once)
    const ulonglong2* h2s = (const ulonglong2*)h_sh + 5 * s;   // matvec slice
    float4* pmy = &part4[tid];                                  // worker store
    const float4* pp1 = &part4[1 * HID + j];                    // owner reads
    const float4* pp2 = &part4[2 * HID + j];
    const float4* pp3 = &part4[3 * HID + j];
    const float4* pp4 = &part4[4 * HID + j];

    float4 xq = owner ? __ldg(&g_xp4[j]) : make_float4(0.f, 0.f, 0.f, 0.f);

    for (int t = 0; t < SEQ; t += 2) {
        LSTM_STEP(t)
        LSTM_STEP(t + 1)
    }

    // final FC
    if (tid < NCLS) {
        float sfc = fc_b[tid];
        const float* fw = fc_w + tid * HID;
#pragma unroll 4
        for (int k = 0; k < HID; k++) sfc += fw[k] * h_sh[k];
        out[tid] = sfc;
    }
}

// ---------------------------------------------------------------------------
extern "C" void kernel_launch(void* const* d_in, const int* in_sizes, int n_in,
                              void* d_out, int out_size) {
    const int*   seq  = (const int*)d_in[0];
    const float* emb  = (const float*)d_in[1];
    const float* W_ih = (const float*)d_in[2];
    const float* W_hh = (const float*)d_in[3];
    const float* b_ih = (const float*)d_in[4];
    const float* b_hh = (const float*)d_in[5];
    const float* fc_w = (const float*)d_in[6];
    const float* fc_b = (const float*)d_in[7];
    float* out = (float*)d_out;

    proj_kernel<<<SEQ / TB, G4>>>(seq, emb, W_ih, b_ih, b_hh);
    lstm_kernel<<<1, NTL>>>(W_hh, fc_w, fc_b, out);
}